// round 5
// baseline (speedup 1.0000x reference)
#include <cuda_runtime.h>
#include <math.h>

#define BATCH 2048

// ---------------- scratch (device globals; no allocation allowed) ----------------
__device__ float g_conv1[BATCH * 21632];       // [B][32][26*26]   (~177 MB)
__device__ float g_pool [BATCH * 9216];        // [B][64*12*12]    (~75 MB)
__device__ float g_fc1p [8 * BATCH * 128];     // split-K partials (8 MB)
__device__ float g_ang  [BATCH * 10];          // angles

// ======================= conv1: [B,1,28,28] -> relu -> [B,32,26,26] =======================
__global__ __launch_bounds__(256) void conv1_kernel(
    const float* __restrict__ x, const float* __restrict__ w,
    const float* __restrict__ bias) {
  int b = blockIdx.x;
  __shared__ float si[784];
  __shared__ float sw[288];
  __shared__ float sb[32];
  const float* xb = x + b * 784;
  for (int i = threadIdx.x; i < 784; i += 256) si[i] = xb[i];
  for (int i = threadIdx.x; i < 288; i += 256) sw[i] = w[i];
  if (threadIdx.x < 32) sb[threadIdx.x] = bias[threadIdx.x];
  __syncthreads();
  float* ob = g_conv1 + b * 21632;
  for (int idx = threadIdx.x; idx < 21632; idx += 256) {
    int oc = idx / 676;
    int pos = idx - oc * 676;
    int oy = pos / 26, ox = pos - oy * 26;
    const float* wp = sw + oc * 9;
    const float* ip = si + oy * 28 + ox;
    float acc = sb[oc];
#pragma unroll
    for (int ky = 0; ky < 3; ky++)
#pragma unroll
      for (int kx = 0; kx < 3; kx++)
        acc = fmaf(wp[ky * 3 + kx], ip[ky * 28 + kx], acc);
    ob[idx] = fmaxf(acc, 0.f);
  }
}

// ====== conv2 + relu + maxpool fused: [B,32,26,26] -> [B,64,24,24] -> [B,9216] flat ======
// block = (oc-group of 16, batch). 192 threads, 3 spatial positions each, 48 accs.
#define C2_SMEM ((21632 + 4608 + 16) * 4)
__global__ __launch_bounds__(192) void conv2_pool_kernel(
    const float* __restrict__ w, const float* __restrict__ bias) {
  extern __shared__ float sm[];
  float* si  = sm;            // input image 32*676
  float* swt = sm + 21632;    // weights, layout [ic*9+t][16 oc]
  float* sb  = swt + 4608;
  int ocg = blockIdx.x, b = blockIdx.y;
  int tid = threadIdx.x;
  const float4* inp4 = (const float4*)(g_conv1 + b * 21632);
  for (int i = tid; i < 5408; i += 192) ((float4*)si)[i] = inp4[i];
  for (int i = tid; i < 4608; i += 192) {
    int ocl = i & 15, r = i >> 4;
    swt[i] = w[(ocg * 16 + ocl) * 288 + r];
  }
  if (tid < 16) sb[tid] = bias[ocg * 16 + tid];
  __syncthreads();

  int p0 = tid, p1 = tid + 192, p2 = tid + 384;
  int off0 = (p0 / 24) * 26 + (p0 % 24);
  int off1 = (p1 / 24) * 26 + (p1 % 24);
  int off2 = (p2 / 24) * 26 + (p2 % 24);
  float acc0[16], acc1[16], acc2[16];
#pragma unroll
  for (int oc = 0; oc < 16; oc++) { acc0[oc] = sb[oc]; acc1[oc] = sb[oc]; acc2[oc] = sb[oc]; }

#pragma unroll 1
  for (int ic = 0; ic < 32; ic++) {
    const float* ipc = si + ic * 676;
#pragma unroll
    for (int ky = 0; ky < 3; ky++)
#pragma unroll
      for (int kx = 0; kx < 3; kx++) {
        int t = ky * 3 + kx;
        float i0 = ipc[ky * 26 + kx + off0];
        float i1 = ipc[ky * 26 + kx + off1];
        float i2 = ipc[ky * 26 + kx + off2];
        const float4* wp4 = (const float4*)(swt + (ic * 9 + t) * 16);
        float wv[16];
        *(float4*)&wv[0]  = wp4[0];
        *(float4*)&wv[4]  = wp4[1];
        *(float4*)&wv[8]  = wp4[2];
        *(float4*)&wv[12] = wp4[3];
#pragma unroll
        for (int oc = 0; oc < 16; oc++) {
          acc0[oc] = fmaf(wv[oc], i0, acc0[oc]);
          acc1[oc] = fmaf(wv[oc], i1, acc1[oc]);
          acc2[oc] = fmaf(wv[oc], i2, acc2[oc]);
        }
      }
  }
  __syncthreads();
  // stash conv outputs in smem (reuse input region), layout [oc][576]
#pragma unroll
  for (int oc = 0; oc < 16; oc++) {
    si[oc * 576 + p0] = acc0[oc];
    si[oc * 576 + p1] = acc1[oc];
    si[oc * 576 + p2] = acc2[oc];
  }
  __syncthreads();
  // 2x2 maxpool + relu, write flattened  idx = c*144 + py*12 + px
  float* ob = g_pool + b * 9216 + ocg * 16 * 144;
  for (int idx = tid; idx < 2304; idx += 192) {
    int oc = idx / 144, pp = idx - oc * 144;
    int py = pp / 12, px = pp - py * 12;
    const float* base = si + oc * 576 + py * 48 + px * 2;
    float m = fmaxf(fmaxf(base[0], base[1]), fmaxf(base[24], base[25]));
    ob[oc * 144 + pp] = fmaxf(m, 0.f);
  }
}

// ============== fc1: [2048,9216] x [128,9216]^T, split-K=8, deterministic partials ==============
__global__ __launch_bounds__(256) void fc1_kernel(const float* __restrict__ W) {
  __shared__ float sA[8][132];
  __shared__ float sB[8][132];
  int bm = blockIdx.x, bk = blockIdx.y;
  int tid = threadIdx.x;
  int row_l = tid >> 1;
  int part = tid & 1;
  const float* Abase = g_pool + (bm * 128 + row_l) * 9216 + bk * 1152 + part * 4;
  const float* Bbase = W + row_l * 9216 + bk * 1152 + part * 4;
  int tx = tid & 15, ty = tid >> 4;
  float acc[8][8];
#pragma unroll
  for (int i = 0; i < 8; i++)
#pragma unroll
    for (int j = 0; j < 8; j++) acc[i][j] = 0.f;

#pragma unroll 1
  for (int kt = 0; kt < 1152; kt += 8) {
    float4 va = *(const float4*)(Abase + kt);
    float4 vb = *(const float4*)(Bbase + kt);
    __syncthreads();
    sA[part * 4 + 0][row_l] = va.x; sA[part * 4 + 1][row_l] = va.y;
    sA[part * 4 + 2][row_l] = va.z; sA[part * 4 + 3][row_l] = va.w;
    sB[part * 4 + 0][row_l] = vb.x; sB[part * 4 + 1][row_l] = vb.y;
    sB[part * 4 + 2][row_l] = vb.z; sB[part * 4 + 3][row_l] = vb.w;
    __syncthreads();
#pragma unroll
    for (int kk = 0; kk < 8; kk++) {
      float ra[8], rb[8];
      *(float4*)&ra[0] = *(const float4*)&sA[kk][ty * 8];
      *(float4*)&ra[4] = *(const float4*)&sA[kk][ty * 8 + 4];
      *(float4*)&rb[0] = *(const float4*)&sB[kk][tx * 8];
      *(float4*)&rb[4] = *(const float4*)&sB[kk][tx * 8 + 4];
#pragma unroll
      for (int i = 0; i < 8; i++)
#pragma unroll
        for (int j = 0; j < 8; j++) acc[i][j] = fmaf(ra[i], rb[j], acc[i][j]);
    }
  }
  float* outp = g_fc1p + bk * (BATCH * 128) + (bm * 128) * 128;
#pragma unroll
  for (int i = 0; i < 8; i++)
#pragma unroll
    for (int j = 0; j < 8; j++)
      outp[(ty * 8 + i) * 128 + tx * 8 + j] = acc[i][j];
}

// ============== fc2: sum partials + bias + relu -> fc2 -> sigmoid*2pi -> angles ==============
__global__ __launch_bounds__(128) void fc2_kernel(
    const float* __restrict__ fc1_b, const float* __restrict__ fc2_w,
    const float* __restrict__ fc2_b) {
  int b = blockIdx.x;
  __shared__ float h[128];
  int k = threadIdx.x;
  float acc = fc1_b[k];
#pragma unroll
  for (int s = 0; s < 8; s++) acc += g_fc1p[s * (BATCH * 128) + b * 128 + k];
  h[k] = fmaxf(acc, 0.f);
  __syncthreads();
  if (k < 10) {
    float z = fc2_b[k];
#pragma unroll 4
    for (int j = 0; j < 128; j++) z = fmaf(h[j], fc2_w[k * 128 + j], z);
    g_ang[b * 10 + k] = 6.2831853071795864769f / (1.f + expf(-z));
  }
}

// =================================== quantum circuit ===================================
__device__ __forceinline__ float2 cmul(float2 a, float2 b) {
  return make_float2(fmaf(a.x, b.x, -a.y * b.y), fmaf(a.x, b.y, a.y * b.x));
}
__device__ __forceinline__ float2 cadd(float2 a, float2 b) {
  return make_float2(a.x + b.x, a.y + b.y);
}

// generic single-qubit gate on bit position bp (wire w -> bp = 9-w)
__device__ __forceinline__ void gate1(float2* psi, int tid, int bp,
                                      float2 u00, float2 u01, float2 u10, float2 u11) {
  for (int p = tid; p < 512; p += 256) {
    int lo = p & ((1 << bp) - 1);
    int i0 = ((p >> bp) << (bp + 1)) | lo;
    int i1 = i0 | (1 << bp);
    float2 x0 = psi[i0], x1 = psi[i1];
    psi[i0] = cadd(cmul(u00, x0), cmul(u01, x1));
    psi[i1] = cadd(cmul(u10, x0), cmul(u11, x1));
  }
  __syncthreads();
}

__global__ __launch_bounds__(256) void quantum_kernel(
    const float* __restrict__ theta0, const float* __restrict__ theta_rz,
    const float* __restrict__ theta_ps, const float* __restrict__ rot_p,
    float* __restrict__ out) {
  int b = blockIdx.x, tid = threadIdx.x;
  __shared__ float2 psi[1024];
  __shared__ float2 sv[10][2];   // per-wire state after all leading single-qubit gates
  __shared__ float sev[10];
  const float* a = g_ang + b * 10;
  const float PI = 3.14159265358979323846f;

  if (tid < 10) sev[tid] = 0.f;

  if (tid == 0) {
    // All gates before the first 2-qubit gate act on a product state.
    // RX gates compose: RX(t1)RX(t2)=RX(t1+t2).
    for (int k = 0; k < 10; k++) {
      float tot = theta0[k] + a[k];
      if (k == 1) tot += a[1];          // extra RX(a1) on wire 1
      if (k == 5) tot += -PI * 0.25f;   // fixed RX(-pi/4) on wire 5
      float c, s;
      sincosf(0.5f * tot, &s, &c);
      float2 v0 = make_float2(c, 0.f);
      float2 v1 = make_float2(0.f, -s);
      if (k == 2) {  // RY(a2)
        float cy, sy; sincosf(0.5f * a[2], &sy, &cy);
        float2 n0 = make_float2(cy * v0.x - sy * v1.x, cy * v0.y - sy * v1.y);
        float2 n1 = make_float2(sy * v0.x + cy * v1.x, sy * v0.y + cy * v1.y);
        v0 = n0; v1 = n1;
      }
      if (k == 3) {  // RZ(a3)
        float ch, sh; sincosf(0.5f * a[3], &sh, &ch);
        v0 = cmul(v0, make_float2(ch, -sh));
        v1 = cmul(v1, make_float2(ch, sh));
      }
      if (k == 4) v1 = make_float2(-v1.y, v1.x);                 // S
      if (k == 5) { const float r = 0.70710678118654752f;        // T
        v1 = cmul(v1, make_float2(r, r)); }
      if (k == 6) {  // RZ(theta_rz)
        float ch, sh; sincosf(0.5f * theta_rz[0], &sh, &ch);
        v0 = cmul(v0, make_float2(ch, -sh));
        v1 = cmul(v1, make_float2(ch, sh));
      }
      if (k == 7) {  // SX
        float2 n0 = make_float2(0.5f * (v0.x - v0.y + v1.x + v1.y),
                                0.5f * (v0.x + v0.y + v1.y - v1.x));
        float2 n1 = make_float2(0.5f * (v0.x + v0.y + v1.x - v1.y),
                                0.5f * (v0.y - v0.x + v1.x + v1.y));
        v0 = n0; v1 = n1;
      }
      sv[k][0] = v0; sv[k][1] = v1;
    }
  }
  __syncthreads();

  // psi[i] = prod_k sv[k][bit_k(i)],  bit_k = (i >> (9-k)) & 1
  for (int i = tid; i < 1024; i += 256) {
    float2 amp = sv[0][(i >> 9) & 1];
#pragma unroll
    for (int k = 1; k < 10; k++) amp = cmul(amp, sv[k][(i >> (9 - k)) & 1]);
    psi[i] = amp;
  }
  __syncthreads();

  // CZ(0,5) CNOT(0,5) CY(0,5): net = Y*X*Z = -i*I on target when wire0=1
  // -> multiply every amplitude with bit9 set by -i.
  for (int i = tid; i < 1024; i += 256)
    if (i & 512) { float2 p = psi[i]; psi[i] = make_float2(p.y, -p.x); }
  __syncthreads();

  // CY(3,8): control bit6(64), target bit1(2)
  for (int i = tid; i < 1024; i += 256)
    if ((i & 64) && !(i & 2)) {
      float2 p0 = psi[i], p1 = psi[i | 2];
      psi[i] = make_float2(p1.y, -p1.x);       // -i * p1
      psi[i | 2] = make_float2(-p0.y, p0.x);   //  i * p0
    }
  __syncthreads();

  // SWAP(2,3): bits 128,64
  for (int i = tid; i < 1024; i += 256)
    if ((i & 128) && !(i & 64)) {
      int j = i ^ 192;
      float2 t = psi[i]; psi[i] = psi[j]; psi[j] = t;
    }
  __syncthreads();

  // CSWAP(4,5,6): control bit5(32), swap bits 16 & 8
  for (int i = tid; i < 1024; i += 256)
    if ((i & 32) && (i & 16) && !(i & 8)) {
      int j = i ^ 24;
      float2 t = psi[i]; psi[i] = psi[j]; psi[j] = t;
    }
  __syncthreads();

  // Toffoli(8,5,0): controls bit1(2) & bit4(16), target bit9(512)
  for (int i = tid; i < 1024; i += 256)
    if ((i & 2) && (i & 16) && !(i & 512)) {
      int j = i | 512;
      float2 t = psi[i]; psi[i] = psi[j]; psi[j] = t;
    }
  __syncthreads();

  // Phase(theta_ps) on wire8 (bit 2), Phase(a7) on wire7 (bit 4) — fused pass
  {
    float c8, s8, c7, s7;
    sincosf(theta_ps[0], &s8, &c8);
    sincosf(a[7], &s7, &c7);
    float2 e8 = make_float2(c8, s8), e7 = make_float2(c7, s7);
    for (int i = tid; i < 1024; i += 256) {
      float2 p = psi[i];
      if (i & 2) p = cmul(p, e8);
      if (i & 4) p = cmul(p, e7);
      psi[i] = p;
    }
  }
  __syncthreads();

  // Rot(phi,th,om) on wire4 (bp 5) and Rot(a6,a7,a8) on wire5 (bp 4)
  {
    float c, s, sp, cp, sm, cm;
    sincosf(0.5f * rot_p[1], &s, &c);
    sincosf(-0.5f * (rot_p[0] + rot_p[2]), &sp, &cp);
    sincosf(0.5f * (rot_p[0] - rot_p[2]), &sm, &cm);
    gate1(psi, tid, 5,
          make_float2(cp * c, sp * c), make_float2(-cm * s, -sm * s),
          make_float2(cm * s, -sm * s), make_float2(cp * c, -sp * c));
    sincosf(0.5f * a[7], &s, &c);
    sincosf(-0.5f * (a[6] + a[8]), &sp, &cp);
    sincosf(0.5f * (a[6] - a[8]), &sm, &cm);
    gate1(psi, tid, 4,
          make_float2(cp * c, sp * c), make_float2(-cm * s, -sm * s),
          make_float2(cm * s, -sm * s), make_float2(cp * c, -sp * c));
  }

  // <Y_k> = 2 * sum_pairs Im(conj(p0) * p1)
  for (int k = 0; k < 10; k++) {
    int bp = 9 - k;
    float part = 0.f;
    for (int p = tid; p < 512; p += 256) {
      int lo = p & ((1 << bp) - 1);
      int i0 = ((p >> bp) << (bp + 1)) | lo;
      float2 a0 = psi[i0], a1 = psi[i0 | (1 << bp)];
      part += a0.x * a1.y - a0.y * a1.x;
    }
#pragma unroll
    for (int off = 16; off; off >>= 1)
      part += __shfl_down_sync(0xffffffffu, part, off);
    if ((tid & 31) == 0) atomicAdd(&sev[k], 2.f * part);
  }
  __syncthreads();

  if (tid < 10) {
    float m = -1e30f;
#pragma unroll
    for (int j = 0; j < 10; j++) m = fmaxf(m, sev[j]);
    float se = 0.f;
#pragma unroll
    for (int j = 0; j < 10; j++) se += expf(sev[j] - m);
    out[b * 10 + tid] = sev[tid] - m - logf(se);
  }
}

// =================================== launch ===================================
extern "C" void kernel_launch(void* const* d_in, const int* in_sizes, int n_in,
                              void* d_out, int out_size) {
  const float* x        = (const float*)d_in[0];
  const float* conv1_w  = (const float*)d_in[1];
  const float* conv1_b  = (const float*)d_in[2];
  const float* conv2_w  = (const float*)d_in[3];
  const float* conv2_b  = (const float*)d_in[4];
  const float* fc1_w    = (const float*)d_in[5];
  const float* fc1_b    = (const float*)d_in[6];
  const float* fc2_w    = (const float*)d_in[7];
  const float* fc2_b    = (const float*)d_in[8];
  const float* theta0   = (const float*)d_in[9];
  const float* theta_rz = (const float*)d_in[10];
  const float* theta_ps = (const float*)d_in[11];
  const float* rot_p    = (const float*)d_in[12];
  float* out = (float*)d_out;

  cudaFuncSetAttribute(conv2_pool_kernel,
                       cudaFuncAttributeMaxDynamicSharedMemorySize, C2_SMEM);

  conv1_kernel<<<BATCH, 256>>>(x, conv1_w, conv1_b);
  conv2_pool_kernel<<<dim3(4, BATCH), 192, C2_SMEM>>>(conv2_w, conv2_b);
  fc1_kernel<<<dim3(16, 8), 256>>>(fc1_w);
  fc2_kernel<<<BATCH, 128>>>(fc1_b, fc2_w, fc2_b);
  quantum_kernel<<<BATCH, 256>>>(theta0, theta_rz, theta_ps, rot_p, out);
}

// round 7
// speedup vs baseline: 1.2485x; 1.2485x over previous
#include <cuda_runtime.h>
#include <math.h>

#define BATCH 2048
typedef unsigned long long ull;

// ---------------- scratch (device globals; no allocation allowed) ----------------
__device__ float g_conv1[BATCH * 21632];       // [B][32][26*26]
__device__ float g_pool [BATCH * 9216];        // [B][64*12*12]
__device__ float g_fc1p [16 * BATCH * 128];    // split-K partials (16.8 MB)
__device__ float g_ang  [BATCH * 10];          // angles

// ---------------- packed f32x2 helpers (Blackwell 2x fp32) ----------------
__device__ __forceinline__ ull ffma2(ull a, ull b, ull c) {
  ull d;
  asm("fma.rn.f32x2 %0, %1, %2, %3;" : "=l"(d) : "l"(a), "l"(b), "l"(c));
  return d;
}
__device__ __forceinline__ ull pack2(float lo, float hi) {
  ull r;
  asm("mov.b64 %0, {%1, %2};" : "=l"(r) : "f"(lo), "f"(hi));
  return r;
}
__device__ __forceinline__ void unpack2(ull v, float& lo, float& hi) {
  asm("mov.b64 {%0, %1}, %2;" : "=f"(lo), "=f"(hi) : "l"(v));
}

// ======================= conv1: [B,1,28,28] -> relu -> [B,32,26,26] =======================
__global__ __launch_bounds__(256) void conv1_kernel(
    const float* __restrict__ x, const float* __restrict__ w,
    const float* __restrict__ bias) {
  int b = blockIdx.x;
  __shared__ float si[784];
  __shared__ float sw[288];
  __shared__ float sb[32];
  const float* xb = x + b * 784;
  for (int i = threadIdx.x; i < 784; i += 256) si[i] = xb[i];
  for (int i = threadIdx.x; i < 288; i += 256) sw[i] = w[i];
  if (threadIdx.x < 32) sb[threadIdx.x] = bias[threadIdx.x];
  __syncthreads();
  float* ob = g_conv1 + b * 21632;
  for (int idx = threadIdx.x; idx < 21632; idx += 256) {
    int oc = idx / 676;
    int pos = idx - oc * 676;
    int oy = pos / 26, ox = pos - oy * 26;
    const float* wp = sw + oc * 9;
    const float* ip = si + oy * 28 + ox;
    float acc = sb[oc];
#pragma unroll
    for (int ky = 0; ky < 3; ky++)
#pragma unroll
      for (int kx = 0; kx < 3; kx++)
        acc = fmaf(wp[ky * 3 + kx], ip[ky * 28 + kx], acc);
    ob[idx] = fmaxf(acc, 0.f);
  }
}

// ====== conv2 + relu + maxpool fused, f32x2 packed: [B,32,26,26] -> [B,9216] flat ======
// block = (oc-group of 16, batch). 192 threads, 3 spatial positions each, 24 packed accs.
#define C2_SMEM ((21632 + 4608 + 16) * 4)
__global__ __launch_bounds__(192) void conv2_pool_kernel(
    const float* __restrict__ w, const float* __restrict__ bias) {
  extern __shared__ __align__(16) float sm[];
  float* si  = sm;            // input image 32*676
  float* swt = sm + 21632;    // weights, layout [ic*9+t][16 oc]  (oc pairs adjacent)
  float* sb  = swt + 4608;
  int ocg = blockIdx.x, b = blockIdx.y;
  int tid = threadIdx.x;
  const float4* inp4 = (const float4*)(g_conv1 + b * 21632);
  for (int i = tid; i < 5408; i += 192) ((float4*)si)[i] = inp4[i];
  for (int i = tid; i < 4608; i += 192) {
    int ocl = i & 15, r = i >> 4;
    swt[i] = w[(ocg * 16 + ocl) * 288 + r];
  }
  if (tid < 16) sb[tid] = bias[ocg * 16 + tid];
  __syncthreads();

  int p0 = tid, p1 = tid + 192, p2 = tid + 384;
  int off0 = (p0 / 24) * 26 + (p0 % 24);
  int off1 = (p1 / 24) * 26 + (p1 % 24);
  int off2 = (p2 / 24) * 26 + (p2 % 24);
  ull acc0[8], acc1[8], acc2[8];   // 8 packed oc-pairs per position
#pragma unroll
  for (int j = 0; j < 8; j++) {
    ull bj = pack2(sb[2 * j], sb[2 * j + 1]);
    acc0[j] = bj; acc1[j] = bj; acc2[j] = bj;
  }

#pragma unroll 1
  for (int ic = 0; ic < 32; ic++) {
    const float* ipc = si + ic * 676;
#pragma unroll
    for (int ky = 0; ky < 3; ky++)
#pragma unroll
      for (int kx = 0; kx < 3; kx++) {
        int t = ky * 3 + kx;
        ull b0 = pack2(ipc[ky * 26 + kx + off0], ipc[ky * 26 + kx + off0]);
        ull b1 = pack2(ipc[ky * 26 + kx + off1], ipc[ky * 26 + kx + off1]);
        ull b2 = pack2(ipc[ky * 26 + kx + off2], ipc[ky * 26 + kx + off2]);
        const ulonglong2* wp2 = (const ulonglong2*)(swt + (ic * 9 + t) * 16);
        ulonglong2 wA = wp2[0], wB = wp2[1], wC = wp2[2], wD = wp2[3];
        ull w2[8];
        w2[0] = wA.x; w2[1] = wA.y; w2[2] = wB.x; w2[3] = wB.y;
        w2[4] = wC.x; w2[5] = wC.y; w2[6] = wD.x; w2[7] = wD.y;
#pragma unroll
        for (int j = 0; j < 8; j++) {
          acc0[j] = ffma2(w2[j], b0, acc0[j]);
          acc1[j] = ffma2(w2[j], b1, acc1[j]);
          acc2[j] = ffma2(w2[j], b2, acc2[j]);
        }
      }
  }
  __syncthreads();
  // stash conv outputs in smem (reuse input region), layout [oc][576]
#pragma unroll
  for (int j = 0; j < 8; j++) {
    float lo, hi;
    unpack2(acc0[j], lo, hi);
    si[(2 * j) * 576 + p0] = lo; si[(2 * j + 1) * 576 + p0] = hi;
    unpack2(acc1[j], lo, hi);
    si[(2 * j) * 576 + p1] = lo; si[(2 * j + 1) * 576 + p1] = hi;
    unpack2(acc2[j], lo, hi);
    si[(2 * j) * 576 + p2] = lo; si[(2 * j + 1) * 576 + p2] = hi;
  }
  __syncthreads();
  // 2x2 maxpool + relu, write flattened  idx = c*144 + py*12 + px
  float* ob = g_pool + b * 9216 + ocg * 16 * 144;
  for (int idx = tid; idx < 2304; idx += 192) {
    int oc = idx / 144, pp = idx - oc * 144;
    int py = pp / 12, px = pp - py * 12;
    const float* base = si + oc * 576 + py * 48 + px * 2;
    float m = fmaxf(fmaxf(base[0], base[1]), fmaxf(base[24], base[25]));
    ob[oc * 144 + pp] = fmaxf(m, 0.f);
  }
}

// ===== fc1: [2048,9216] x [128,9216]^T, split-K=16, f32x2 packed, deterministic =====
__global__ __launch_bounds__(256) void fc1_kernel(const float* __restrict__ W) {
  __shared__ __align__(16) float sA[8][132];
  __shared__ __align__(16) float sB[8][132];
  int bm = blockIdx.x, bk = blockIdx.y;
  int tid = threadIdx.x;
  int row_l = tid >> 1;
  int part = tid & 1;
  const float* Abase = g_pool + (bm * 128 + row_l) * 9216 + bk * 576 + part * 4;
  const float* Bbase = W + row_l * 9216 + bk * 576 + part * 4;
  int tx = tid & 15, ty = tid >> 4;
  ull acc[8][4];   // 8 rows x 4 packed col-pairs
#pragma unroll
  for (int i = 0; i < 8; i++)
#pragma unroll
    for (int j = 0; j < 4; j++) acc[i][j] = 0ull;

#pragma unroll 1
  for (int kt = 0; kt < 576; kt += 8) {
    float4 va = *(const float4*)(Abase + kt);
    float4 vb = *(const float4*)(Bbase + kt);
    __syncthreads();
    sA[part * 4 + 0][row_l] = va.x; sA[part * 4 + 1][row_l] = va.y;
    sA[part * 4 + 2][row_l] = va.z; sA[part * 4 + 3][row_l] = va.w;
    sB[part * 4 + 0][row_l] = vb.x; sB[part * 4 + 1][row_l] = vb.y;
    sB[part * 4 + 2][row_l] = vb.z; sB[part * 4 + 3][row_l] = vb.w;
    __syncthreads();
#pragma unroll
    for (int kk = 0; kk < 8; kk++) {
      float ra[8];
      *(float4*)&ra[0] = *(const float4*)&sA[kk][ty * 8];
      *(float4*)&ra[4] = *(const float4*)&sA[kk][ty * 8 + 4];
      const ulonglong2* rbp = (const ulonglong2*)&sB[kk][tx * 8];
      ulonglong2 rb01 = rbp[0], rb23 = rbp[1];
      ull rb2[4] = {rb01.x, rb01.y, rb23.x, rb23.y};
#pragma unroll
      for (int i = 0; i < 8; i++) {
        ull rai = pack2(ra[i], ra[i]);
#pragma unroll
        for (int j = 0; j < 4; j++) acc[i][j] = ffma2(rb2[j], rai, acc[i][j]);
      }
    }
  }
  float* outp = g_fc1p + bk * (BATCH * 128) + (bm * 128) * 128;
#pragma unroll
  for (int i = 0; i < 8; i++)
#pragma unroll
    for (int j = 0; j < 4; j++) {
      float lo, hi;
      unpack2(acc[i][j], lo, hi);
      outp[(ty * 8 + i) * 128 + tx * 8 + 2 * j]     = lo;
      outp[(ty * 8 + i) * 128 + tx * 8 + 2 * j + 1] = hi;
    }
}

// ============== fc2: sum partials + bias + relu -> fc2 -> sigmoid*2pi -> angles ==============
__global__ __launch_bounds__(128) void fc2_kernel(
    const float* __restrict__ fc1_b, const float* __restrict__ fc2_w,
    const float* __restrict__ fc2_b) {
  int b = blockIdx.x;
  __shared__ float h[128];
  int k = threadIdx.x;
  float acc = fc1_b[k];
#pragma unroll
  for (int s = 0; s < 16; s++) acc += g_fc1p[s * (BATCH * 128) + b * 128 + k];
  h[k] = fmaxf(acc, 0.f);
  __syncthreads();
  if (k < 10) {
    float z = fc2_b[k];
#pragma unroll 4
    for (int j = 0; j < 128; j++) z = fmaf(h[j], fc2_w[k * 128 + j], z);
    g_ang[b * 10 + k] = 6.2831853071795864769f / (1.f + expf(-z));
  }
}

// =================================== quantum circuit ===================================
__device__ __forceinline__ float2 cmul(float2 a, float2 b) {
  return make_float2(fmaf(a.x, b.x, -a.y * b.y), fmaf(a.x, b.y, a.y * b.x));
}
__device__ __forceinline__ float2 cadd(float2 a, float2 b) {
  return make_float2(a.x + b.x, a.y + b.y);
}

// generic single-qubit gate on bit position bp (wire w -> bp = 9-w)
__device__ __forceinline__ void gate1(float2* psi, int tid, int bp,
                                      float2 u00, float2 u01, float2 u10, float2 u11) {
  for (int p = tid; p < 512; p += 256) {
    int lo = p & ((1 << bp) - 1);
    int i0 = ((p >> bp) << (bp + 1)) | lo;
    int i1 = i0 | (1 << bp);
    float2 x0 = psi[i0], x1 = psi[i1];
    psi[i0] = cadd(cmul(u00, x0), cmul(u01, x1));
    psi[i1] = cadd(cmul(u10, x0), cmul(u11, x1));
  }
  __syncthreads();
}

__global__ __launch_bounds__(256) void quantum_kernel(
    const float* __restrict__ theta0, const float* __restrict__ theta_rz,
    const float* __restrict__ theta_ps, const float* __restrict__ rot_p,
    float* __restrict__ out) {
  int b = blockIdx.x, tid = threadIdx.x;
  __shared__ float2 psi[1024];
  __shared__ float2 sv[10][2];   // per-wire state after all leading single-qubit gates
  __shared__ float sev[10];
  const float* a = g_ang + b * 10;
  const float PI = 3.14159265358979323846f;

  if (tid < 10) sev[tid] = 0.f;

  if (tid == 0) {
    // All gates before the first 2-qubit gate act on a product state.
    for (int k = 0; k < 10; k++) {
      float tot = theta0[k] + a[k];
      if (k == 1) tot += a[1];          // extra RX(a1) on wire 1
      if (k == 5) tot += -PI * 0.25f;   // fixed RX(-pi/4) on wire 5
      float c, s;
      sincosf(0.5f * tot, &s, &c);
      float2 v0 = make_float2(c, 0.f);
      float2 v1 = make_float2(0.f, -s);
      if (k == 2) {  // RY(a2)
        float cy, sy; sincosf(0.5f * a[2], &sy, &cy);
        float2 n0 = make_float2(cy * v0.x - sy * v1.x, cy * v0.y - sy * v1.y);
        float2 n1 = make_float2(sy * v0.x + cy * v1.x, sy * v0.y + cy * v1.y);
        v0 = n0; v1 = n1;
      }
      if (k == 3) {  // RZ(a3)
        float ch, sh; sincosf(0.5f * a[3], &sh, &ch);
        v0 = cmul(v0, make_float2(ch, -sh));
        v1 = cmul(v1, make_float2(ch, sh));
      }
      if (k == 4) v1 = make_float2(-v1.y, v1.x);                 // S
      if (k == 5) { const float r = 0.70710678118654752f;        // T
        v1 = cmul(v1, make_float2(r, r)); }
      if (k == 6) {  // RZ(theta_rz)
        float ch, sh; sincosf(0.5f * theta_rz[0], &sh, &ch);
        v0 = cmul(v0, make_float2(ch, -sh));
        v1 = cmul(v1, make_float2(ch, sh));
      }
      if (k == 7) {  // SX
        float2 n0 = make_float2(0.5f * (v0.x - v0.y + v1.x + v1.y),
                                0.5f * (v0.x + v0.y + v1.y - v1.x));
        float2 n1 = make_float2(0.5f * (v0.x + v0.y + v1.x - v1.y),
                                0.5f * (v0.y - v0.x + v1.x + v1.y));
        v0 = n0; v1 = n1;
      }
      sv[k][0] = v0; sv[k][1] = v1;
    }
  }
  __syncthreads();

  // psi[i] = prod_k sv[k][bit_k(i)],  bit_k = (i >> (9-k)) & 1
  for (int i = tid; i < 1024; i += 256) {
    float2 amp = sv[0][(i >> 9) & 1];
#pragma unroll
    for (int k = 1; k < 10; k++) amp = cmul(amp, sv[k][(i >> (9 - k)) & 1]);
    psi[i] = amp;
  }
  __syncthreads();

  // CZ(0,5) CNOT(0,5) CY(0,5): net = -i*I on target when wire0=1
  for (int i = tid; i < 1024; i += 256)
    if (i & 512) { float2 p = psi[i]; psi[i] = make_float2(p.y, -p.x); }
  __syncthreads();

  // CY(3,8): control bit6(64), target bit1(2)
  for (int i = tid; i < 1024; i += 256)
    if ((i & 64) && !(i & 2)) {
      float2 p0 = psi[i], p1 = psi[i | 2];
      psi[i] = make_float2(p1.y, -p1.x);       // -i * p1
      psi[i | 2] = make_float2(-p0.y, p0.x);   //  i * p0
    }
  __syncthreads();

  // SWAP(2,3): bits 128,64
  for (int i = tid; i < 1024; i += 256)
    if ((i & 128) && !(i & 64)) {
      int j = i ^ 192;
      float2 t = psi[i]; psi[i] = psi[j]; psi[j] = t;
    }
  __syncthreads();

  // CSWAP(4,5,6): control bit5(32), swap bits 16 & 8
  for (int i = tid; i < 1024; i += 256)
    if ((i & 32) && (i & 16) && !(i & 8)) {
      int j = i ^ 24;
      float2 t = psi[i]; psi[i] = psi[j]; psi[j] = t;
    }
  __syncthreads();

  // Toffoli(8,5,0): controls bit1(2) & bit4(16), target bit9(512)
  for (int i = tid; i < 1024; i += 256)
    if ((i & 2) && (i & 16) && !(i & 512)) {
      int j = i | 512;
      float2 t = psi[i]; psi[i] = psi[j]; psi[j] = t;
    }
  __syncthreads();

  // Phase(theta_ps) on wire8 (bit 2), Phase(a7) on wire7 (bit 4) — fused pass
  {
    float c8, s8, c7, s7;
    sincosf(theta_ps[0], &s8, &c8);
    sincosf(a[7], &s7, &c7);
    float2 e8 = make_float2(c8, s8), e7 = make_float2(c7, s7);
    for (int i = tid; i < 1024; i += 256) {
      float2 p = psi[i];
      if (i & 2) p = cmul(p, e8);
      if (i & 4) p = cmul(p, e7);
      psi[i] = p;
    }
  }
  __syncthreads();

  // Rot(phi,th,om) on wire4 (bp 5) and Rot(a6,a7,a8) on wire5 (bp 4)
  {
    float c, s, sp, cp, sm, cm;
    sincosf(0.5f * rot_p[1], &s, &c);
    sincosf(-0.5f * (rot_p[0] + rot_p[2]), &sp, &cp);
    sincosf(0.5f * (rot_p[0] - rot_p[2]), &sm, &cm);
    gate1(psi, tid, 5,
          make_float2(cp * c, sp * c), make_float2(-cm * s, -sm * s),
          make_float2(cm * s, -sm * s), make_float2(cp * c, -sp * c));
    sincosf(0.5f * a[7], &s, &c);
    sincosf(-0.5f * (a[6] + a[8]), &sp, &cp);
    sincosf(0.5f * (a[6] - a[8]), &sm, &cm);
    gate1(psi, tid, 4,
          make_float2(cp * c, sp * c), make_float2(-cm * s, -sm * s),
          make_float2(cm * s, -sm * s), make_float2(cp * c, -sp * c));
  }

  // <Y_k> = 2 * sum_pairs Im(conj(p0) * p1)
  for (int k = 0; k < 10; k++) {
    int bp = 9 - k;
    float part = 0.f;
    for (int p = tid; p < 512; p += 256) {
      int lo = p & ((1 << bp) - 1);
      int i0 = ((p >> bp) << (bp + 1)) | lo;
      float2 a0 = psi[i0], a1 = psi[i0 | (1 << bp)];
      part += a0.x * a1.y - a0.y * a1.x;
    }
#pragma unroll
    for (int off = 16; off; off >>= 1)
      part += __shfl_down_sync(0xffffffffu, part, off);
    if ((tid & 31) == 0) atomicAdd(&sev[k], 2.f * part);
  }
  __syncthreads();

  if (tid < 10) {
    float m = -1e30f;
#pragma unroll
    for (int j = 0; j < 10; j++) m = fmaxf(m, sev[j]);
    float se = 0.f;
#pragma unroll
    for (int j = 0; j < 10; j++) se += expf(sev[j] - m);
    out[b * 10 + tid] = sev[tid] - m - logf(se);
  }
}

// =================================== launch ===================================
extern "C" void kernel_launch(void* const* d_in, const int* in_sizes, int n_in,
                              void* d_out, int out_size) {
  const float* x        = (const float*)d_in[0];
  const float* conv1_w  = (const float*)d_in[1];
  const float* conv1_b  = (const float*)d_in[2];
  const float* conv2_w  = (const float*)d_in[3];
  const float* conv2_b  = (const float*)d_in[4];
  const float* fc1_w    = (const float*)d_in[5];
  const float* fc1_b    = (const float*)d_in[6];
  const float* fc2_w    = (const float*)d_in[7];
  const float* fc2_b    = (const float*)d_in[8];
  const float* theta0   = (const float*)d_in[9];
  const float* theta_rz = (const float*)d_in[10];
  const float* theta_ps = (const float*)d_in[11];
  const float* rot_p    = (const float*)d_in[12];
  float* out = (float*)d_out;

  cudaFuncSetAttribute(conv2_pool_kernel,
                       cudaFuncAttributeMaxDynamicSharedMemorySize, C2_SMEM);

  conv1_kernel<<<BATCH, 256>>>(x, conv1_w, conv1_b);
  conv2_pool_kernel<<<dim3(4, BATCH), 192, C2_SMEM>>>(conv2_w, conv2_b);
  fc1_kernel<<<dim3(16, 16), 256>>>(fc1_w);
  fc2_kernel<<<BATCH, 128>>>(fc1_b, fc2_w, fc2_b);
  quantum_kernel<<<BATCH, 256>>>(theta0, theta_rz, theta_ps, rot_p, out);
}